// round 2
// baseline (speedup 1.0000x reference)
#include <cuda_runtime.h>
#include <math_constants.h>

#define HH 128
#define WW 128
#define HWSZ 16384
#define CIN 64
#define CMID 16
#define NMAX 4
#define RAD 4
#define TILE 16
#define HALO 24   // TILE + 2*RAD
#define F2STR 18  // padded per-pixel stride in floats (conflict-free for float2)

// Scratch (device globals — no allocation allowed)
__device__ float g_f1[NMAX * HWSZ * CMID];   // [N, HW, 16]
__device__ float g_f2[NMAX * HWSZ * CMID];   // [N, HW, 16]
__device__ float g_oup[NMAX * HWSZ * 2];     // [N, HW, 2] upsampled out

__device__ __forceinline__ int refl(int i, int n) {
    if (i < 0) i = -i;
    if (i >= n) i = 2 * n - 2 - i;
    return i;
}

// Kernel 1: f1/f2 = 1x1 convs (64->16), plus bilinear align-corners upsample of out.
__global__ void prep_kernel(const float* __restrict__ delta,
                            const float* __restrict__ outc,
                            const float* __restrict__ w1,
                            const float* __restrict__ b1,
                            const float* __restrict__ w2,
                            const float* __restrict__ b2,
                            int N) {
    __shared__ float s_w1[CMID * CIN];
    __shared__ float s_w2[CMID * CIN];
    for (int i = threadIdx.x; i < CMID * CIN; i += blockDim.x) {
        s_w1[i] = w1[i];
        s_w2[i] = w2[i];
    }
    __syncthreads();

    int p = blockIdx.x * blockDim.x + threadIdx.x;
    if (p >= N * HWSZ) return;
    int n = p >> 14;
    int yx = p & (HWSZ - 1);

    float acc1[CMID], acc2[CMID];
#pragma unroll
    for (int o = 0; o < CMID; o++) { acc1[o] = b1[o]; acc2[o] = b2[o]; }

    const float* dptr = delta + (size_t)n * CIN * HWSZ + yx;
#pragma unroll 1
    for (int c0 = 0; c0 < CIN; c0 += 4) {
        float d0 = dptr[(c0 + 0) * HWSZ];
        float d1 = dptr[(c0 + 1) * HWSZ];
        float d2 = dptr[(c0 + 2) * HWSZ];
        float d3 = dptr[(c0 + 3) * HWSZ];
#pragma unroll
        for (int o = 0; o < CMID; o++) {
            float4 wa = *(const float4*)(s_w1 + o * CIN + c0);
            float4 wb = *(const float4*)(s_w2 + o * CIN + c0);
            acc1[o] = fmaf(d0, wa.x, fmaf(d1, wa.y, fmaf(d2, wa.z, fmaf(d3, wa.w, acc1[o]))));
            acc2[o] = fmaf(d0, wb.x, fmaf(d1, wb.y, fmaf(d2, wb.z, fmaf(d3, wb.w, acc2[o]))));
        }
    }

    float4* f1o = (float4*)(g_f1 + (size_t)p * CMID);
    float4* f2o = (float4*)(g_f2 + (size_t)p * CMID);
#pragma unroll
    for (int j = 0; j < 4; j++) {
        f1o[j] = make_float4(acc1[4*j], acc1[4*j+1], acc1[4*j+2], acc1[4*j+3]);
        f2o[j] = make_float4(acc2[4*j], acc2[4*j+1], acc2[4*j+2], acc2[4*j+3]);
    }

    // Bilinear upsample (align_corners=True) of out [N,2,64,64] -> per-pixel 2 vals
    int y = yx >> 7, x = yx & 127;
    const float scl = 63.0f / 127.0f;
    float sy = y * scl;
    float sx = x * scl;
    int y0i = (int)sy;
    int x0i = (int)sx;
    if (y0i > 62) y0i = 62;  // guard (sy<=63)
    if (x0i > 62) x0i = 62;
    float wy = sy - y0i, wx = sx - x0i;
    int y1i = y0i + 1;
    int x1i = x0i + 1;
    const float* ob = outc + (size_t)n * 2 * 4096;
#pragma unroll
    for (int c = 0; c < 2; c++) {
        const float* oc = ob + c * 4096;
        float v00 = oc[y0i * 64 + x0i];
        float v01 = oc[y0i * 64 + x1i];
        float v10 = oc[y1i * 64 + x0i];
        float v11 = oc[y1i * 64 + x1i];
        float top = v00 * (1.0f - wx) + v01 * wx;
        float bot = v10 * (1.0f - wx) + v11 * wx;
        g_oup[(size_t)p * 2 + c] = top * (1.0f - wy) + bot * wy;
    }
}

// Kernel 2: per 16x16 tile — load reflect-mapped 24x24 halos of f2 / out_up into
// smem, then per-pixel: 81-tap squared-distance logits + fused online softmax
// + weighted aggregation of out_up.
__global__ __launch_bounds__(256) void main_kernel(
    const float* __restrict__ ab,
    const float* __restrict__ gdp,
    const float* __restrict__ gsp,
    float* __restrict__ outr) {
    __shared__ float s_f2[HALO * HALO * F2STR];  // 41472 B
    __shared__ float s_ou[HALO * HALO * 2];      //  4608 B

    int tx = threadIdx.x, ty = threadIdx.y;
    int tid = ty * TILE + tx;
    int x0 = blockIdx.x * TILE, y0 = blockIdx.y * TILE;
    int n = blockIdx.z;

    // Halo load with reflect mapping
    for (int i = tid; i < HALO * HALO; i += 256) {
        int hy = i / HALO, hx = i - hy * HALO;
        int gy = refl(y0 - RAD + hy, HH);
        int gx = refl(x0 - RAD + hx, WW);
        int gp = (n << 14) + (gy << 7) + gx;
        const float4* src = (const float4*)(g_f2 + (size_t)gp * CMID);
        float4 a0 = src[0], a1 = src[1], a2 = src[2], a3 = src[3];
        float* dst = s_f2 + i * F2STR;
        float2* d2 = (float2*)dst;
        d2[0] = make_float2(a0.x, a0.y);
        d2[1] = make_float2(a0.z, a0.w);
        d2[2] = make_float2(a1.x, a1.y);
        d2[3] = make_float2(a1.z, a1.w);
        d2[4] = make_float2(a2.x, a2.y);
        d2[5] = make_float2(a2.z, a2.w);
        d2[6] = make_float2(a3.x, a3.y);
        d2[7] = make_float2(a3.z, a3.w);
        const float2 ov = *(const float2*)(g_oup + (size_t)gp * 2);
        *(float2*)(s_ou + i * 2) = ov;
    }
    __syncthreads();

    int x = x0 + tx, y = y0 + ty;
    int yx = (y << 7) + x;
    int p = (n << 14) + yx;

    float f1r[CMID];
    {
        const float4* f1p = (const float4*)(g_f1 + (size_t)p * CMID);
#pragma unroll
        for (int j = 0; j < 4; j++) {
            float4 v = f1p[j];
            f1r[4*j] = v.x; f1r[4*j+1] = v.y; f1r[4*j+2] = v.z; f1r[4*j+3] = v.w;
        }
    }

    const float gd = *gdp;
    const float gs = *gsp;
    const float* abp = ab + (size_t)n * 81 * HWSZ + yx;

    float m = -CUDART_INF_F;
    float s = 0.0f, a0 = 0.0f, a1 = 0.0f;

#pragma unroll 1
    for (int k = 0; k < 81; k++) {
        int dy = k / 9;
        int dx = k - dy * 9;
        int hidx = (ty + dy) * HALO + (tx + dx);
        const float2* f2p = (const float2*)(s_f2 + hidx * F2STR);
        float dist = 0.0f;
#pragma unroll
        for (int j = 0; j < 8; j++) {
            float2 v = f2p[j];
            float e0 = f1r[2*j]   - v.x;
            float e1 = f1r[2*j+1] - v.y;
            dist = fmaf(e0, e0, dist);
            dist = fmaf(e1, e1, dist);
        }
        float logit = fmaf(gs, abp[(size_t)k * HWSZ], -gd * dist);
        float2 ou = *(const float2*)(s_ou + hidx * 2);

        // branchless online softmax update
        float nm = fmaxf(m, logit);
        float r = __expf(m - nm);      // == 1 when m unchanged
        float w = __expf(logit - nm);
        s = fmaf(s, r, w);
        a0 = fmaf(a0, r, w * ou.x);
        a1 = fmaf(a1, r, w * ou.y);
        m = nm;
    }

    float inv = 1.0f / s;
    outr[((size_t)(n * 2) << 14) + yx] = a0 * inv;
    outr[((size_t)(n * 2 + 1) << 14) + yx] = a1 * inv;
}

extern "C" void kernel_launch(void* const* d_in, const int* in_sizes, int n_in,
                              void* d_out, int out_size) {
    const float* delta = (const float*)d_in[0];
    const float* outc  = (const float*)d_in[1];
    const float* ab    = (const float*)d_in[2];
    const float* w1    = (const float*)d_in[3];
    const float* b1    = (const float*)d_in[4];
    const float* w2    = (const float*)d_in[5];
    const float* b2    = (const float*)d_in[6];
    const float* gd    = (const float*)d_in[7];
    const float* gs    = (const float*)d_in[8];

    int N = in_sizes[0] / (CIN * HWSZ);
    if (N > NMAX) N = NMAX;

    prep_kernel<<<(N * HWSZ + 255) / 256, 256>>>(delta, outc, w1, b1, w2, b2, N);
    main_kernel<<<dim3(WW / TILE, HH / TILE, N), dim3(TILE, TILE)>>>(
        ab, gd, gs, (float*)d_out);
}